// round 1
// baseline (speedup 1.0000x reference)
#include <cuda_runtime.h>
#include <math.h>
#include <math_constants.h>

#define BSZ  128
#define TLEN 500
#define ISZ  700
#define HSZ  256
#define OSZ  20
#define BJ0  0.01f

// Scratch (static __device__ arrays are the sanctioned scratch mechanism)
__device__ float g_hpre[(size_t)BSZ * TLEN * HSZ];  // 65.5 MB: x@Wi^T + biases
__device__ float g_wit[ISZ * HSZ];                  // W_i2h transposed [K=700][N=256]
__device__ float g_wth[HSZ * HSZ];                  // W_h2h transposed [j][i]

// ---------------------------------------------------------------------------
// Prep: transpose W_i2h (256x700 -> 700x256) and W_h2h (256x256 -> 256x256)
// ---------------------------------------------------------------------------
__global__ void prep_kernel(const float* __restrict__ Wi,
                            const float* __restrict__ Wh) {
    int idx = blockIdx.x * blockDim.x + threadIdx.x;
    if (idx < ISZ * HSZ) {
        int k = idx / HSZ, n = idx % HSZ;
        g_wit[idx] = Wi[n * ISZ + k];
    }
    if (idx < HSZ * HSZ) {
        int j = idx / HSZ, i = idx % HSZ;
        g_wth[idx] = Wh[i * HSZ + j];
    }
}

// ---------------------------------------------------------------------------
// GEMM: g_hpre[m][n] = sum_k x[m][k] * g_wit[k][n] + b_i2h[n] + b_h2h[n]
// M=64000, N=256, K=700.  BM=BN=128, BK=8, 256 threads, 8x8 microtile.
// ---------------------------------------------------------------------------
__global__ void __launch_bounds__(256) gemm_kernel(
    const float* __restrict__ A,
    const float* __restrict__ bi,
    const float* __restrict__ bh) {
    const int N = HSZ, K = ISZ;
    __shared__ float As[8][128];
    __shared__ float Bs[8][128];

    int tid = threadIdx.x;
    int bm = blockIdx.x * 128;
    int bn = blockIdx.y * 128;

    int tx = tid & 15;   // col group 0..15
    int ty = tid >> 4;   // row group 0..15

    float acc[8][8];
#pragma unroll
    for (int i = 0; i < 8; i++)
#pragma unroll
        for (int j = 0; j < 8; j++) acc[i][j] = 0.f;

    int arow  = tid >> 1;          // 0..127
    int acol4 = (tid & 1) * 4;     // 0 or 4
    int brow  = tid >> 5;          // 0..7
    int bcol4 = (tid & 31) * 4;    // 0..124

    for (int k0 = 0; k0 < K; k0 += 8) {
        // Load A tile (x rows), guard K tail (700 % 8 == 4; 700 % 4 == 0)
        float4 av = make_float4(0.f, 0.f, 0.f, 0.f);
        int ac = k0 + acol4;
        if (ac < K)
            av = *(const float4*)(A + (size_t)(bm + arow) * K + ac);
        As[acol4 + 0][arow] = av.x;
        As[acol4 + 1][arow] = av.y;
        As[acol4 + 2][arow] = av.z;
        As[acol4 + 3][arow] = av.w;

        // Load B tile (transposed W_i2h, row-major [K][N])
        float4 bv = make_float4(0.f, 0.f, 0.f, 0.f);
        int bk = k0 + brow;
        if (bk < K)
            bv = *(const float4*)(g_wit + (size_t)bk * N + bn + bcol4);
        *(float4*)&Bs[brow][bcol4] = bv;

        __syncthreads();
#pragma unroll
        for (int kk = 0; kk < 8; kk++) {
            float af[8], bf[8];
#pragma unroll
            for (int i = 0; i < 8; i++) af[i] = As[kk][ty * 8 + i];
#pragma unroll
            for (int j = 0; j < 8; j++) bf[j] = Bs[kk][tx * 8 + j];
#pragma unroll
            for (int i = 0; i < 8; i++)
#pragma unroll
                for (int j = 0; j < 8; j++) acc[i][j] += af[i] * bf[j];
        }
        __syncthreads();
    }

#pragma unroll
    for (int i = 0; i < 8; i++) {
        int m = bm + ty * 8 + i;
#pragma unroll
        for (int j = 0; j < 8; j++) {
            int n = bn + tx * 8 + j;
            g_hpre[(size_t)m * N + n] = acc[i][j] + bi[n] + bh[n];
        }
    }
}

// ---------------------------------------------------------------------------
// Scan: one CTA per batch element, 256 threads (one per hidden neuron).
// Spikes become binary after step 0 -> recurrent matvec is a gated column sum
// driven by a 256-bit ballot mask. Output layer (O=20) via 160-thread partials
// + warp-0 shuffle log-softmax.
// ---------------------------------------------------------------------------
__global__ void __launch_bounds__(256) scan_kernel(
    const float* __restrict__ Wo,        // W_h2o [20][256]
    const float* __restrict__ bo_bias,   // b_h2o [20]
    const float* __restrict__ tau_adp_o, // [20]
    const float* __restrict__ tau_m_h,   // [256]
    const float* __restrict__ tau_m_o,   // [20]
    const float* __restrict__ h0,        // [B,256]
    const float* __restrict__ o0,        // [B,20]
    float* __restrict__ out)             // [B,20,500]
{
    __shared__ float    s_wo[OSZ * 257];   // padded to kill bank conflicts
    __shared__ float    s_spkf[HSZ];       // float spikes (step 0 only)
    __shared__ unsigned s_mask[2][8];      // double-buffered spike bitmask
    __shared__ float    s_part[OSZ * 8];   // output partial sums

    const int b    = blockIdx.x;
    const int tid  = threadIdx.x;
    const int lane = tid & 31;
    const int wid  = tid >> 5;

    // W_h2o -> SMEM (padded stride 257)
    for (int idx = tid; idx < OSZ * HSZ; idx += 256) {
        int o = idx >> 8, j = idx & 255;
        s_wo[o * 257 + j] = Wo[idx];
    }

    const float a_h      = expf(-1.f / tau_m_h[tid]);
    const float one_m_ah = 1.f - a_h;

    float h_mem    = h0[(size_t)b * HSZ + tid];
    float spk_prev = h_mem;     // carry0: h_spk initialized to h0 (continuous!)
    s_spkf[tid]    = spk_prev;

    // Output-layer state lives in warp-0 lane registers (lanes 0..19)
    float o_mem = 0.f, o_spk = 0.f, bo = 0.f;
    float alpha_o = 0.f, ro_o = 0.f, one_m_ao = 0.f, one_m_ro = 0.f, bias_o = 0.f;
    if (tid < OSZ) {
        o_mem    = o0[(size_t)b * OSZ + tid];
        o_spk    = o_mem;
        bo       = BJ0;
        alpha_o  = expf(-1.f / tau_m_o[tid]);
        ro_o     = expf(-1.f / tau_adp_o[tid]);
        one_m_ao = 1.f - alpha_o;
        one_m_ro = 1.f - ro_o;
        bias_o   = bo_bias[tid];
    }
    __syncthreads();

    const float* hp     = g_hpre + (size_t)b * TLEN * HSZ + tid;
    const float* wtcol  = g_wth + tid;
    float pre = hp[0];
    int p = 0;

    for (int t = 0; t < TLEN; ++t) {
        float acc = pre;
        if (t + 1 < TLEN) pre = hp[(size_t)(t + 1) * HSZ];   // software prefetch

        if (t == 0) {
            // continuous initial spikes: full FMA matvec
#pragma unroll 8
            for (int j = 0; j < HSZ; ++j)
                acc += wtcol[(size_t)j * HSZ] * s_spkf[j];
        } else {
            // binary spikes: gated column sums via bitmask walk
#pragma unroll
            for (int w8 = 0; w8 < 8; ++w8) {
                unsigned m = s_mask[p][w8];
                const float* basep = wtcol + (size_t)(w8 * 32) * HSZ;
                while (m) {
                    int j = __ffs(m) - 1;
                    m &= m - 1;
                    acc += basep[(size_t)j * HSZ];
                }
            }
        }

        // hidden ALIF update (B_h == BJ0 constant, b_h is dead code)
        h_mem = h_mem * a_h + one_m_ah * acc - BJ0 * spk_prev;
        bool sp = (h_mem - BJ0) > 0.f;
        spk_prev = sp ? 1.f : 0.f;

        unsigned bal = __ballot_sync(0xffffffffu, sp);
        if (lane == 0) s_mask[p ^ 1][wid] = bal;
        __syncthreads();

        // output layer partials: thread = (o in 0..19) x (part in 0..7)
        if (tid < OSZ * 8) {
            int o    = tid >> 3;
            int part = tid & 7;
            unsigned m = s_mask[p ^ 1][part];
            const float* wrow = s_wo + o * 257 + part * 32;
            float ps = 0.f;
            while (m) {
                int j = __ffs(m) - 1;
                m &= m - 1;
                ps += wrow[j];
            }
            s_part[o * 8 + part] = ps;
        }
        __syncthreads();

        if (wid == 0) {
            float om;
            if (lane < OSZ) {
                float oin = bias_o;
#pragma unroll
                for (int k2 = 0; k2 < 8; k2++) oin += s_part[lane * 8 + k2];
                bo = ro_o * bo + one_m_ro * o_spk;
                float Bo = BJ0 + 1.8f * bo;
                o_mem = o_mem * alpha_o + one_m_ao * oin - Bo * o_spk;
                o_spk = ((o_mem - Bo) > 0.f) ? 1.f : 0.f;
                om = o_mem;
            } else {
                om = -CUDART_INF_F;
            }
            // log_softmax over the 20 outputs (full-warp shuffles)
            float mx = om;
#pragma unroll
            for (int off = 16; off; off >>= 1)
                mx = fmaxf(mx, __shfl_xor_sync(0xffffffffu, mx, off));
            float e = (lane < OSZ) ? expf(om - mx) : 0.f;
            float s = e;
#pragma unroll
            for (int off = 16; off; off >>= 1)
                s += __shfl_xor_sync(0xffffffffu, s, off);
            if (lane < OSZ)
                out[((size_t)b * OSZ + lane) * TLEN + t] = om - mx - logf(s);
        }
        p ^= 1;
    }
}

// ---------------------------------------------------------------------------
extern "C" void kernel_launch(void* const* d_in, const int* in_sizes, int n_in,
                              void* d_out, int out_size) {
    const float* x         = (const float*)d_in[0];
    const float* W_i2h     = (const float*)d_in[1];
    const float* b_i2h     = (const float*)d_in[2];
    const float* W_h2h     = (const float*)d_in[3];
    const float* b_h2h     = (const float*)d_in[4];
    const float* W_h2o     = (const float*)d_in[5];
    const float* b_h2o     = (const float*)d_in[6];
    // d_in[7] = tau_adp_h (dead: hidden layer is non-adaptive, B_h == b_j0)
    const float* tau_adp_o = (const float*)d_in[8];
    const float* tau_m_h   = (const float*)d_in[9];
    const float* tau_m_o   = (const float*)d_in[10];
    const float* h0        = (const float*)d_in[11];
    const float* o0        = (const float*)d_in[12];
    float* out = (float*)d_out;

    prep_kernel<<<(ISZ * HSZ + 255) / 256, 256>>>(W_i2h, W_h2h);

    dim3 grid_gemm(BSZ * TLEN / 128, HSZ / 128);   // (500, 2)
    gemm_kernel<<<grid_gemm, 256>>>(x, b_i2h, b_h2h);

    scan_kernel<<<BSZ, 256>>>(W_h2o, b_h2o, tau_adp_o, tau_m_h, tau_m_o,
                              h0, o0, out);
}

// round 2
// speedup vs baseline: 3.1656x; 3.1656x over previous
#include <cuda_runtime.h>
#include <math.h>
#include <math_constants.h>

#define BSZ  128
#define TLEN 500
#define ISZ  700
#define HSZ  256
#define OSZ  20
#define BJ0  0.01f

// Scratch
__device__ float g_hpre[(size_t)BSZ * TLEN * HSZ];  // 65.5 MB: x@Wi^T + biases
__device__ float g_wit[ISZ * HSZ];                  // W_i2h^T  [K=700][N=256]
__device__ float g_wth[HSZ * HSZ];                  // W_h2h^T  [j][i]

// ---------------------------------------------------------------------------
__global__ void prep_kernel(const float* __restrict__ Wi,
                            const float* __restrict__ Wh) {
    int idx = blockIdx.x * blockDim.x + threadIdx.x;
    if (idx < ISZ * HSZ) {
        int k = idx / HSZ, n = idx % HSZ;
        g_wit[idx] = Wi[n * ISZ + k];
    }
    if (idx < HSZ * HSZ) {
        int j = idx / HSZ, i = idx % HSZ;
        g_wth[idx] = Wh[i * HSZ + j];
    }
}

// ---------------------------------------------------------------------------
// GEMM: g_hpre[m][n] = x[m][:] . g_wit[:][n] + bi[n] + bh[n]
// M=64000, N=256, K=700. 128x128x8 tiles, double-buffered smem.
// ---------------------------------------------------------------------------
__global__ void __launch_bounds__(256, 2) gemm_kernel(
    const float* __restrict__ A,
    const float* __restrict__ bi,
    const float* __restrict__ bh) {
    const int N = HSZ, K = ISZ;
    __shared__ float As[2][8][128];
    __shared__ float Bs[2][8][128];

    int tid = threadIdx.x;
    int bm = blockIdx.x * 128;
    int bn = blockIdx.y * 128;
    int tx = tid & 15, ty = tid >> 4;

    float acc[8][8];
#pragma unroll
    for (int i = 0; i < 8; i++)
#pragma unroll
        for (int j = 0; j < 8; j++) acc[i][j] = 0.f;

    int arow  = tid >> 1,  acol4 = (tid & 1) * 4;
    int brow  = tid >> 5,  bcol4 = (tid & 31) * 4;
    const float* Aptr = A + (size_t)(bm + arow) * K;

    // Preload tile 0
    {
        float4 av = make_float4(0.f, 0.f, 0.f, 0.f);
        float4 bv = make_float4(0.f, 0.f, 0.f, 0.f);
        if (acol4 < K) av = *(const float4*)(Aptr + acol4);
        if (brow  < K) bv = *(const float4*)(g_wit + (size_t)brow * N + bn + bcol4);
        As[0][acol4 + 0][arow] = av.x;
        As[0][acol4 + 1][arow] = av.y;
        As[0][acol4 + 2][arow] = av.z;
        As[0][acol4 + 3][arow] = av.w;
        *(float4*)&Bs[0][brow][bcol4] = bv;
    }
    __syncthreads();

    int p = 0;
    for (int k0 = 0; k0 < K; k0 += 8) {
        bool more = (k0 + 8) < K;
        float4 av2 = make_float4(0.f, 0.f, 0.f, 0.f);
        float4 bv2 = make_float4(0.f, 0.f, 0.f, 0.f);
        if (more) {
            int ac = k0 + 8 + acol4;
            int bk = k0 + 8 + brow;
            if (ac < K) av2 = *(const float4*)(Aptr + ac);
            if (bk < K) bv2 = *(const float4*)(g_wit + (size_t)bk * N + bn + bcol4);
        }
#pragma unroll
        for (int kk = 0; kk < 8; kk++) {
            float af[8], bf[8];
#pragma unroll
            for (int i = 0; i < 8; i++) af[i] = As[p][kk][ty * 8 + i];
#pragma unroll
            for (int j = 0; j < 8; j++) bf[j] = Bs[p][kk][tx * 8 + j];
#pragma unroll
            for (int i = 0; i < 8; i++)
#pragma unroll
                for (int j = 0; j < 8; j++) acc[i][j] += af[i] * bf[j];
        }
        if (more) {
            As[p ^ 1][acol4 + 0][arow] = av2.x;
            As[p ^ 1][acol4 + 1][arow] = av2.y;
            As[p ^ 1][acol4 + 2][arow] = av2.z;
            As[p ^ 1][acol4 + 3][arow] = av2.w;
            *(float4*)&Bs[p ^ 1][brow][bcol4] = bv2;
        }
        __syncthreads();
        p ^= 1;
    }

    float biasv[8];
#pragma unroll
    for (int j = 0; j < 8; j++) {
        int n = bn + tx * 8 + j;
        biasv[j] = bi[n] + bh[n];
    }
#pragma unroll
    for (int i = 0; i < 8; i++) {
        size_t m = (size_t)(bm + ty * 8 + i);
        float4 v0, v1;
        v0.x = acc[i][0] + biasv[0]; v0.y = acc[i][1] + biasv[1];
        v0.z = acc[i][2] + biasv[2]; v0.w = acc[i][3] + biasv[3];
        v1.x = acc[i][4] + biasv[4]; v1.y = acc[i][5] + biasv[5];
        v1.z = acc[i][6] + biasv[6]; v1.w = acc[i][7] + biasv[7];
        *(float4*)(g_hpre + m * HSZ + bn + tx * 8)     = v0;
        *(float4*)(g_hpre + m * HSZ + bn + tx * 8 + 4) = v1;
    }
}

// ---------------------------------------------------------------------------
// Scan: 1 CTA/batch, 288 threads: warps 0-7 = 256 hidden neurons,
// warp 8 = output layer (runs concurrently with the hidden matvec).
// Spike set -> shared index list -> 8-wide unrolled gather (MLP=8).
// ---------------------------------------------------------------------------
#define NTH 288

__global__ void __launch_bounds__(NTH) scan_kernel(
    const float* __restrict__ Wo,        // [20][256]
    const float* __restrict__ bo_bias,   // [20]
    const float* __restrict__ tau_adp_o, // [20]
    const float* __restrict__ tau_m_h,   // [256]
    const float* __restrict__ tau_m_o,   // [20]
    const float* __restrict__ h0,        // [B,256]
    const float* __restrict__ o0,        // [B,20]
    float* __restrict__ out)             // [B,20,500]
{
    __shared__ float s_woT[HSZ * 24 + 8];       // transposed Wo, pad 24
    __shared__ float s_spk0[HSZ];               // continuous init "spikes"
    __shared__ __align__(16) int s_idx[HSZ];    // spike index list
    __shared__ int   s_wcnt[2][8];              // per-warp spike counts

    const int b    = blockIdx.x;
    const int tid  = threadIdx.x;
    const int lane = tid & 31;
    const int wid  = tid >> 5;
    const bool hidden = (wid < 8);

    for (int i = tid; i < OSZ * HSZ; i += NTH) {
        int o = i >> 8, j = i & 255;
        s_woT[j * 24 + o] = Wo[i];
    }

    // hidden state
    float a_h = 0.f, one_m_ah = 0.f, h_mem = 0.f, spf = 0.f;
    unsigned bal = 0;
    int sp = 0;
    if (hidden) {
        a_h = expf(-1.f / tau_m_h[tid]);
        one_m_ah = 1.f - a_h;
        h_mem = h0[(size_t)b * HSZ + tid];
        spf = h_mem;                 // carry0: h_spk = h0 (continuous)
        s_spk0[tid] = spf;
    }

    // output state (warp 8, lanes 0..19)
    float o_mem = 0.f, o_spk = 0.f, bo = 0.f;
    float alpha_o = 0.f, ro_o = 0.f, one_m_ao = 0.f, one_m_ro = 0.f, bias_o = 0.f;
    if (!hidden && lane < OSZ) {
        o_mem    = o0[(size_t)b * OSZ + lane];
        o_spk    = o_mem;
        bo       = BJ0;
        alpha_o  = expf(-1.f / tau_m_o[lane]);
        ro_o     = expf(-1.f / tau_adp_o[lane]);
        one_m_ao = 1.f - alpha_o;
        one_m_ro = 1.f - ro_o;
        bias_o   = bo_bias[lane];
    }

    const float* hp = g_hpre + (size_t)b * TLEN * HSZ + tid;
    const float* wt = g_wth + tid;
    float pre = hidden ? __ldcs(hp) : 0.f;
    int cnt = 0;

#pragma unroll 1
    for (int t = 0; t <= TLEN; ++t) {
        // ---- Phase A: scatter last step's spike indices; everyone gets cnt
        if (t >= 1) {
            const int cb = (t - 1) & 1;
            int total = 0, base = 0;
#pragma unroll
            for (int w = 0; w < 8; w++) {
                int c = s_wcnt[cb][w];
                if (w < wid) base += c;
                total += c;
            }
            cnt = total;
            if (hidden && sp)
                s_idx[base + __popc(bal & ((1u << lane) - 1u))] = tid;
        }
        __syncthreads();

        // ---- Phase B (hidden): recurrent matvec + ALIF update + ballot
        if (hidden && t < TLEN) {
            float acc = pre;
            if (t + 1 < TLEN) pre = __ldcs(hp + (size_t)(t + 1) * HSZ);

            float racc = 0.f;
            if (t == 0) {
#pragma unroll 8
                for (int j = 0; j < HSZ; ++j)
                    racc += wt[(size_t)j * HSZ] * s_spk0[j];
            } else {
                int i = 0;
#pragma unroll 1
                for (; i + 8 <= cnt; i += 8) {
                    int4 ja = *(const int4*)(s_idx + i);
                    int4 jb = *(const int4*)(s_idx + i + 4);
                    float w0 = wt[(size_t)ja.x * HSZ];
                    float w1 = wt[(size_t)ja.y * HSZ];
                    float w2 = wt[(size_t)ja.z * HSZ];
                    float w3 = wt[(size_t)ja.w * HSZ];
                    float w4 = wt[(size_t)jb.x * HSZ];
                    float w5 = wt[(size_t)jb.y * HSZ];
                    float w6 = wt[(size_t)jb.z * HSZ];
                    float w7 = wt[(size_t)jb.w * HSZ];
                    racc += ((w0 + w1) + (w2 + w3)) + ((w4 + w5) + (w6 + w7));
                }
#pragma unroll 1
                for (; i < cnt; ++i)
                    racc += wt[(size_t)s_idx[i] * HSZ];
            }
            acc += racc;

            h_mem = h_mem * a_h + one_m_ah * acc - BJ0 * spf;
            sp = (h_mem - BJ0) > 0.f;
            spf = sp ? 1.f : 0.f;
            bal = __ballot_sync(0xffffffffu, sp);
            if (lane == 0) s_wcnt[t & 1][wid] = __popc(bal);
        }

        // ---- Phase B (output warp): layer + log-softmax for step t-1
        if (!hidden && t >= 1) {
            const int to = t - 1;
            float om;
            if (lane < OSZ) {
                float oin = bias_o;
                int i = 0;
#pragma unroll 1
                for (; i + 8 <= cnt; i += 8) {
                    int4 ja = *(const int4*)(s_idx + i);
                    int4 jb = *(const int4*)(s_idx + i + 4);
                    float w0 = s_woT[ja.x * 24 + lane];
                    float w1 = s_woT[ja.y * 24 + lane];
                    float w2 = s_woT[ja.z * 24 + lane];
                    float w3 = s_woT[ja.w * 24 + lane];
                    float w4 = s_woT[jb.x * 24 + lane];
                    float w5 = s_woT[jb.y * 24 + lane];
                    float w6 = s_woT[jb.z * 24 + lane];
                    float w7 = s_woT[jb.w * 24 + lane];
                    oin += ((w0 + w1) + (w2 + w3)) + ((w4 + w5) + (w6 + w7));
                }
#pragma unroll 1
                for (; i < cnt; ++i)
                    oin += s_woT[s_idx[i] * 24 + lane];

                bo = ro_o * bo + one_m_ro * o_spk;
                float Bo = BJ0 + 1.8f * bo;
                o_mem = o_mem * alpha_o + one_m_ao * oin - Bo * o_spk;
                o_spk = ((o_mem - Bo) > 0.f) ? 1.f : 0.f;
                om = o_mem;
            } else {
                om = -CUDART_INF_F;
            }
            float mx = om;
#pragma unroll
            for (int off = 16; off; off >>= 1)
                mx = fmaxf(mx, __shfl_xor_sync(0xffffffffu, mx, off));
            float e = (lane < OSZ) ? expf(om - mx) : 0.f;
            float s = e;
#pragma unroll
            for (int off = 16; off; off >>= 1)
                s += __shfl_xor_sync(0xffffffffu, s, off);
            if (lane < OSZ)
                out[((size_t)b * OSZ + lane) * TLEN + to] = om - mx - logf(s);
        }
        __syncthreads();
    }
}

// ---------------------------------------------------------------------------
extern "C" void kernel_launch(void* const* d_in, const int* in_sizes, int n_in,
                              void* d_out, int out_size) {
    const float* x         = (const float*)d_in[0];
    const float* W_i2h     = (const float*)d_in[1];
    const float* b_i2h     = (const float*)d_in[2];
    const float* W_h2h     = (const float*)d_in[3];
    const float* b_h2h     = (const float*)d_in[4];
    const float* W_h2o     = (const float*)d_in[5];
    const float* b_h2o     = (const float*)d_in[6];
    // d_in[7] = tau_adp_h (dead: hidden layer non-adaptive, B_h == b_j0)
    const float* tau_adp_o = (const float*)d_in[8];
    const float* tau_m_h   = (const float*)d_in[9];
    const float* tau_m_o   = (const float*)d_in[10];
    const float* h0        = (const float*)d_in[11];
    const float* o0        = (const float*)d_in[12];
    float* out = (float*)d_out;

    prep_kernel<<<(ISZ * HSZ + 255) / 256, 256>>>(W_i2h, W_h2h);

    dim3 grid_gemm(BSZ * TLEN / 128, HSZ / 128);   // (500, 2)
    gemm_kernel<<<grid_gemm, 256>>>(x, b_i2h, b_h2h);

    scan_kernel<<<BSZ, NTH>>>(W_h2o, b_h2o, tau_adp_o, tau_m_h, tau_m_o,
                              h0, o0, out);
}

// round 3
// speedup vs baseline: 4.8339x; 1.5270x over previous
#include <cuda_runtime.h>
#include <math.h>
#include <math_constants.h>
#include <stdint.h>

#define BSZ  128
#define TLEN 500
#define ISZ  700
#define HSZ  256
#define OSZ  20
#define BJ0  0.01f

// Scratch
__device__ float g_hpre[(size_t)BSZ * TLEN * HSZ];  // 65.5 MB: x@Wi^T + biases
__device__ float g_wit[ISZ * HSZ];                  // W_i2h^T  [K=700][N=256]
__device__ float g_wth[HSZ * HSZ];                  // W_h2h^T  [j][i]

// ---------------------------------------------------------------------------
__global__ void prep_kernel(const float* __restrict__ Wi,
                            const float* __restrict__ Wh) {
    int idx = blockIdx.x * blockDim.x + threadIdx.x;
    if (idx < ISZ * HSZ) {
        int k = idx / HSZ, n = idx % HSZ;
        g_wit[idx] = Wi[n * ISZ + k];
    }
    if (idx < HSZ * HSZ) {
        int j = idx / HSZ, i = idx % HSZ;
        g_wth[idx] = Wh[i * HSZ + j];
    }
}

// ---------------------------------------------------------------------------
// GEMM: g_hpre[m][n] = x[m][:] . g_wit[:][n] + bi[n] + bh[n]
// M=64000, N=256, K=700. 128x128x8 tiles, double-buffered smem, FFMA2.
// ---------------------------------------------------------------------------
#define FMA2(acc, a, b) \
    asm("fma.rn.f32x2 %0, %1, %2, %0;" : "+l"(acc) : "l"(a), "l"(b))

__global__ void __launch_bounds__(256, 2) gemm_kernel(
    const float* __restrict__ A,
    const float* __restrict__ bi,
    const float* __restrict__ bh) {
    const int N = HSZ, K = ISZ;
    __shared__ __align__(16) float As[2][8][128];
    __shared__ __align__(16) float Bs[2][8][128];

    int tid = threadIdx.x;
    int bm = blockIdx.x * 128;
    int bn = blockIdx.y * 128;
    int tx = tid & 15, ty = tid >> 4;

    unsigned long long acc2[8][4];   // packed f32x2 accumulators (cols 2j,2j+1)
#pragma unroll
    for (int i = 0; i < 8; i++)
#pragma unroll
        for (int j = 0; j < 4; j++) acc2[i][j] = 0ull;

    int arow  = tid >> 1,  acol4 = (tid & 1) * 4;
    int brow  = tid >> 5,  bcol4 = (tid & 31) * 4;
    const float* Aptr = A + (size_t)(bm + arow) * K;

    {
        float4 av = make_float4(0.f, 0.f, 0.f, 0.f);
        float4 bv = make_float4(0.f, 0.f, 0.f, 0.f);
        if (acol4 < K) av = *(const float4*)(Aptr + acol4);
        if (brow  < K) bv = *(const float4*)(g_wit + (size_t)brow * N + bn + bcol4);
        As[0][acol4 + 0][arow] = av.x;
        As[0][acol4 + 1][arow] = av.y;
        As[0][acol4 + 2][arow] = av.z;
        As[0][acol4 + 3][arow] = av.w;
        *(float4*)&Bs[0][brow][bcol4] = bv;
    }
    __syncthreads();

    int p = 0;
    for (int k0 = 0; k0 < K; k0 += 8) {
        bool more = (k0 + 8) < K;
        float4 av2 = make_float4(0.f, 0.f, 0.f, 0.f);
        float4 bv2 = make_float4(0.f, 0.f, 0.f, 0.f);
        if (more) {
            int ac = k0 + 8 + acol4;
            int bk = k0 + 8 + brow;
            if (ac < K) av2 = *(const float4*)(Aptr + ac);
            if (bk < K) bv2 = *(const float4*)(g_wit + (size_t)bk * N + bn + bcol4);
        }
#pragma unroll
        for (int kk = 0; kk < 8; kk++) {
            float4 a0 = *(const float4*)&As[p][kk][ty * 8];
            float4 a1 = *(const float4*)&As[p][kk][ty * 8 + 4];
            const unsigned long long* bp =
                (const unsigned long long*)&Bs[p][kk][tx * 8];
            unsigned long long bb0 = bp[0], bb1 = bp[1], bb2 = bp[2], bb3 = bp[3];
            float af[8] = {a0.x, a0.y, a0.z, a0.w, a1.x, a1.y, a1.z, a1.w};
#pragma unroll
            for (int i = 0; i < 8; i++) {
                unsigned long long aa;
                unsigned ai = __float_as_uint(af[i]);
                asm("mov.b64 %0, {%1, %1};" : "=l"(aa) : "r"(ai));
                FMA2(acc2[i][0], aa, bb0);
                FMA2(acc2[i][1], aa, bb1);
                FMA2(acc2[i][2], aa, bb2);
                FMA2(acc2[i][3], aa, bb3);
            }
        }
        if (more) {
            As[p ^ 1][acol4 + 0][arow] = av2.x;
            As[p ^ 1][acol4 + 1][arow] = av2.y;
            As[p ^ 1][acol4 + 2][arow] = av2.z;
            As[p ^ 1][acol4 + 3][arow] = av2.w;
            *(float4*)&Bs[p ^ 1][brow][bcol4] = bv2;
        }
        __syncthreads();
        p ^= 1;
    }

    float biasv[8];
#pragma unroll
    for (int j = 0; j < 8; j++) {
        int n = bn + tx * 8 + j;
        biasv[j] = bi[n] + bh[n];
    }
#pragma unroll
    for (int i = 0; i < 8; i++) {
        size_t m = (size_t)(bm + ty * 8 + i);
        float r[8];
#pragma unroll
        for (int j = 0; j < 4; j++) {
            unsigned lo, hi;
            asm("mov.b64 {%0, %1}, %2;" : "=r"(lo), "=r"(hi) : "l"(acc2[i][j]));
            r[2 * j]     = __uint_as_float(lo) + biasv[2 * j];
            r[2 * j + 1] = __uint_as_float(hi) + biasv[2 * j + 1];
        }
        float4 v0 = make_float4(r[0], r[1], r[2], r[3]);
        float4 v1 = make_float4(r[4], r[5], r[6], r[7]);
        *(float4*)(g_hpre + m * HSZ + bn + tx * 8)     = v0;
        *(float4*)(g_hpre + m * HSZ + bn + tx * 8 + 4) = v1;
    }
}

// ---------------------------------------------------------------------------
// Scan: cluster of 2 CTAs per batch PAIR. CTA rank r owns neuron slice
// [r*128,(r+1)*128) for BOTH batches, with its 128KB W_h2h^T slice in SMEM.
// 8 hidden warps (2 batches x 128 neurons) + 1 output warp (batch = blockIdx).
// Spike ballots exchanged via st.shared::cluster + split cluster barrier.
// ---------------------------------------------------------------------------
#define NTH 288
#define SCAN_SMEM_FLOATS 38944   // 155,776 bytes

__device__ __forceinline__ void st_peer_u32(uint32_t local_addr, uint32_t rank,
                                            uint32_t val) {
    asm volatile(
        "{.reg .b32 ra; mapa.shared::cluster.u32 ra, %0, %1;"
        " st.shared::cluster.b32 [ra], %2;}"
        :: "r"(local_addr), "r"(rank), "r"(val) : "memory");
}

__device__ __forceinline__ uint32_t smem_u32(const void* p) {
    uint32_t a;
    asm("{ .reg .u64 t; cvta.to.shared.u64 t, %1; cvt.u32.u64 %0, t; }"
        : "=r"(a) : "l"(p));
    return a;
}

__global__ void __launch_bounds__(NTH, 1) __cluster_dims__(2, 1, 1)
scan_kernel(const float* __restrict__ Wo,        // [20][256]
            const float* __restrict__ bo_bias,   // [20]
            const float* __restrict__ tau_adp_o, // [20]
            const float* __restrict__ tau_m_h,   // [256]
            const float* __restrict__ tau_m_o,   // [20]
            const float* __restrict__ h0,        // [B,256]
            const float* __restrict__ o0,        // [B,20]
            float* __restrict__ out)             // [B,20,500]
{
    extern __shared__ float smf[];
    float*    s_wt   = smf;                        // [256][128]
    float*    s_woT  = smf + 32768;                // [256][20]
    float*    s_spk0 = smf + 37888;                // [2][256]
    int*      s_idx  = (int*)(smf + 38400);        // [2][256]
    unsigned* s_bal  = (unsigned*)(smf + 38912);   // [par2][bl2][8]

    const int tid  = threadIdx.x;
    const int lane = tid & 31;
    const int wid  = tid >> 5;
    const int r    = blockIdx.x & 1;               // cluster rank
    const int b0   = blockIdx.x & ~1;              // first batch of pair
    const bool hidden = (wid < 8);

    // --- SMEM init ---
    // W_h2h^T slice: s_wt[j][il] = g_wth[j*256 + r*128 + il]
    for (int i = tid; i < 8192; i += NTH) {        // 8192 float4s
        int j = i >> 5, c = i & 31;
        ((float4*)s_wt)[i] =
            *(const float4*)(g_wth + (size_t)j * HSZ + r * 128 + c * 4);
    }
    // Wo transposed: s_woT[j*20 + o]
    for (int i = tid; i < OSZ * HSZ; i += NTH) {
        int o = i >> 8, j = i & 255;
        s_woT[j * OSZ + o] = Wo[i];
    }
    // initial continuous "spikes" (h0) for both batches
    for (int i = tid; i < 2 * HSZ; i += NTH) {
        int bl = i >> 8, j = i & 255;
        s_spk0[i] = h0[(size_t)(b0 + bl) * HSZ + j];
    }

    // --- per-thread state ---
    const int bl = (hidden ? (tid >> 7) : 0);      // batch-local for hidden
    const int il = tid & 127;                      // local neuron index
    const int q  = (wid & 3);                      // quarter within slice
    const int col = r * 128 + il;                  // global neuron index
    const int gw  = r * 4 + q;                     // ballot word index

    float a_h = 0.f, one_m_ah = 0.f, h_mem = 0.f, spf = 0.f;
    if (hidden) {
        a_h = expf(-1.f / tau_m_h[col]);
        one_m_ah = 1.f - a_h;
        h_mem = h0[(size_t)(b0 + bl) * HSZ + col];
        spf = h_mem;
    }

    // output state: this CTA outputs batch (b0 + r) == blockIdx.x
    float o_mem = 0.f, o_spk = 0.f, bo = 0.f;
    float alpha_o = 0.f, ro_o = 0.f, one_m_ao = 0.f, one_m_ro = 0.f, bias_o = 0.f;
    if (!hidden && lane < OSZ) {
        o_mem    = o0[(size_t)blockIdx.x * OSZ + lane];
        o_spk    = o_mem;
        bo       = BJ0;
        alpha_o  = expf(-1.f / tau_m_o[lane]);
        ro_o     = expf(-1.f / tau_adp_o[lane]);
        one_m_ao = 1.f - alpha_o;
        one_m_ro = 1.f - ro_o;
        bias_o   = bo_bias[lane];
    }
    __syncthreads();

    const float* hp = g_hpre + ((size_t)(b0 + bl) * TLEN) * HSZ + col;
    const float* wcol = s_wt + il;
    float pre = hidden ? __ldcs(hp) : 0.f;
    const uint32_t bal_base = smem_u32(s_bal);
    int cntA[2] = {0, 0};

#pragma unroll 1
    for (int t = 0; t <= TLEN; ++t) {
        // ---- scatter: build index lists from ballots of step t-1 ----
        if (t >= 1) {
            const unsigned* wp0 = s_bal + ((t - 1) & 1) * 16;
#pragma unroll
            for (int bb = 0; bb < 2; bb++) {
                const unsigned* wp = wp0 + bb * 8;
                unsigned w[8];
                int tot = 0;
#pragma unroll
                for (int k2 = 0; k2 < 8; k2++) { w[k2] = wp[k2]; tot += __popc(w[k2]); }
                cntA[bb] = tot;
                if (tid < HSZ) {
                    int wi = tid >> 5, bit = tid & 31;
                    if ((w[wi] >> bit) & 1u) {
                        int pos = 0;
#pragma unroll
                        for (int k2 = 0; k2 < 8; k2++)
                            if (k2 < wi) pos += __popc(w[k2]);
                        pos += __popc(w[wi] & ((1u << bit) - 1u));
                        s_idx[bb * HSZ + pos] = tid;
                    }
                }
            }
        }
        __syncthreads();

        // ---- hidden: recurrent gather + ALIF + ballot ----
        if (hidden && t < TLEN) {
            float acc = pre;
            if (t + 1 < TLEN) pre = __ldcs(hp + (size_t)(t + 1) * HSZ);

            float racc = 0.f;
            if (t == 0) {
                const float* sp0 = s_spk0 + bl * HSZ;
#pragma unroll 8
                for (int j = 0; j < HSZ; ++j)
                    racc += wcol[j * 128] * sp0[j];
            } else {
                const int* lst = s_idx + bl * HSZ;
                const int cnt = cntA[bl];
                int i = 0;
#pragma unroll 1
                for (; i + 8 <= cnt; i += 8) {
                    int4 ja = *(const int4*)(lst + i);
                    int4 jb = *(const int4*)(lst + i + 4);
                    float w0 = wcol[ja.x * 128];
                    float w1 = wcol[ja.y * 128];
                    float w2 = wcol[ja.z * 128];
                    float w3 = wcol[ja.w * 128];
                    float w4 = wcol[jb.x * 128];
                    float w5 = wcol[jb.y * 128];
                    float w6 = wcol[jb.z * 128];
                    float w7 = wcol[jb.w * 128];
                    racc += ((w0 + w1) + (w2 + w3)) + ((w4 + w5) + (w6 + w7));
                }
#pragma unroll 1
                for (; i < cnt; ++i)
                    racc += wcol[lst[i] * 128];
            }
            acc += racc;

            h_mem = h_mem * a_h + one_m_ah * acc - BJ0 * spf;
            int sp = (h_mem - BJ0) > 0.f;
            spf = sp ? 1.f : 0.f;
            unsigned bal = __ballot_sync(0xffffffffu, sp);
            if (lane == 0) {
                int off = (t & 1) * 16 + bl * 8 + gw;
                s_bal[off] = bal;
                st_peer_u32(bal_base + off * 4, (unsigned)(r ^ 1), bal);
            }
        }

        // ---- output warp: layer + log-softmax for step t-1 ----
        if (!hidden && t >= 1) {
            const int to = t - 1;
            float om;
            if (lane < OSZ) {
                float oin = bias_o;
                const int* lst = s_idx + r * HSZ;
                const int cnt = cntA[r];
                int i = 0;
#pragma unroll 1
                for (; i + 8 <= cnt; i += 8) {
                    int4 ja = *(const int4*)(lst + i);
                    int4 jb = *(const int4*)(lst + i + 4);
                    float w0 = s_woT[ja.x * OSZ + lane];
                    float w1 = s_woT[ja.y * OSZ + lane];
                    float w2 = s_woT[ja.z * OSZ + lane];
                    float w3 = s_woT[ja.w * OSZ + lane];
                    float w4 = s_woT[jb.x * OSZ + lane];
                    float w5 = s_woT[jb.y * OSZ + lane];
                    float w6 = s_woT[jb.z * OSZ + lane];
                    float w7 = s_woT[jb.w * OSZ + lane];
                    oin += ((w0 + w1) + (w2 + w3)) + ((w4 + w5) + (w6 + w7));
                }
#pragma unroll 1
                for (; i < cnt; ++i)
                    oin += s_woT[lst[i] * OSZ + lane];

                bo = ro_o * bo + one_m_ro * o_spk;
                float Bo = BJ0 + 1.8f * bo;
                o_mem = o_mem * alpha_o + one_m_ao * oin - Bo * o_spk;
                o_spk = ((o_mem - Bo) > 0.f) ? 1.f : 0.f;
                om = o_mem;
            } else {
                om = -CUDART_INF_F;
            }
            float mx = om;
#pragma unroll
            for (int off = 16; off; off >>= 1)
                mx = fmaxf(mx, __shfl_xor_sync(0xffffffffu, mx, off));
            float e = (lane < OSZ) ? expf(om - mx) : 0.f;
            float s = e;
#pragma unroll
            for (int off = 16; off; off >>= 1)
                s += __shfl_xor_sync(0xffffffffu, s, off);
            if (lane < OSZ)
                out[((size_t)blockIdx.x * OSZ + lane) * TLEN + to] = om - mx - logf(s);
        }

        // ---- cluster barrier: ballots(t) visible across the pair ----
        asm volatile("barrier.cluster.arrive.aligned;" ::: "memory");
        asm volatile("barrier.cluster.wait.aligned;" ::: "memory");
    }
}

// ---------------------------------------------------------------------------
extern "C" void kernel_launch(void* const* d_in, const int* in_sizes, int n_in,
                              void* d_out, int out_size) {
    const float* x         = (const float*)d_in[0];
    const float* W_i2h     = (const float*)d_in[1];
    const float* b_i2h     = (const float*)d_in[2];
    const float* W_h2h     = (const float*)d_in[3];
    const float* b_h2h     = (const float*)d_in[4];
    const float* W_h2o     = (const float*)d_in[5];
    const float* b_h2o     = (const float*)d_in[6];
    // d_in[7] = tau_adp_h (dead: hidden layer non-adaptive, B_h == b_j0)
    const float* tau_adp_o = (const float*)d_in[8];
    const float* tau_m_h   = (const float*)d_in[9];
    const float* tau_m_o   = (const float*)d_in[10];
    const float* h0        = (const float*)d_in[11];
    const float* o0        = (const float*)d_in[12];
    float* out = (float*)d_out;

    prep_kernel<<<(ISZ * HSZ + 255) / 256, 256>>>(W_i2h, W_h2h);

    dim3 grid_gemm(BSZ * TLEN / 128, HSZ / 128);   // (500, 2)
    gemm_kernel<<<grid_gemm, 256>>>(x, b_i2h, b_h2h);

    static int smem_set = 0;
    if (!smem_set) {
        cudaFuncSetAttribute(scan_kernel,
                             cudaFuncAttributeMaxDynamicSharedMemorySize,
                             SCAN_SMEM_FLOATS * 4);
        smem_set = 1;
    }
    scan_kernel<<<BSZ, NTH, SCAN_SMEM_FLOATS * 4>>>(
        W_h2o, b_h2o, tau_adp_o, tau_m_h, tau_m_o, h0, o0, out);
}

// round 4
// speedup vs baseline: 5.3798x; 1.1129x over previous
#include <cuda_runtime.h>
#include <math.h>
#include <math_constants.h>
#include <stdint.h>

#define BSZ  128
#define TLEN 500
#define ISZ  700
#define HSZ  256
#define OSZ  20
#define BJ0  0.01f

// Scratch
__device__ float g_hpre[(size_t)BSZ * TLEN * HSZ];  // 65.5 MB
__device__ float g_wit[ISZ * HSZ];                  // W_i2h^T [700][256]
__device__ float g_wth[HSZ * HSZ];                  // W_h2h^T [j][i]

// ---------------------------------------------------------------------------
__global__ void prep_kernel(const float* __restrict__ Wi,
                            const float* __restrict__ Wh) {
    int idx = blockIdx.x * blockDim.x + threadIdx.x;
    if (idx < ISZ * HSZ) {
        int k = idx / HSZ, n = idx % HSZ;
        g_wit[idx] = Wi[n * ISZ + k];
    }
    if (idx < HSZ * HSZ) {
        int j = idx / HSZ, i = idx % HSZ;
        g_wth[idx] = Wh[i * HSZ + j];
    }
}

// ---------------------------------------------------------------------------
// Persistent GEMM: g_hpre[m][n] = x[m][:].g_wit[:][n] + bi[n] + bh[n]
// M=64000,N=256,K=700. 128x128x8 tiles, double-buffered smem, FFMA2.
// grid = 296 (2 CTAs/SM exactly), each CTA loops over tiles.
// ---------------------------------------------------------------------------
#define FMA2(acc, a, b) \
    asm("fma.rn.f32x2 %0, %1, %2, %0;" : "+l"(acc) : "l"(a), "l"(b))

#define GEMM_TILES 1000
#define GEMM_GRID  296

__global__ void __launch_bounds__(256, 2) gemm_kernel(
    const float* __restrict__ A,
    const float* __restrict__ bi,
    const float* __restrict__ bh) {
    const int N = HSZ, K = ISZ;
    __shared__ __align__(16) float As[2][8][128];
    __shared__ __align__(16) float Bs[2][8][128];

    int tid = threadIdx.x;
    int tx = tid & 15, ty = tid >> 4;
    int arow  = tid >> 1,  acol4 = (tid & 1) * 4;
    int brow  = tid >> 5,  bcol4 = (tid & 31) * 4;

    for (int tile = blockIdx.x; tile < GEMM_TILES; tile += GEMM_GRID) {
        int bm = (tile >> 1) * 128;
        int bn = (tile & 1) * 128;
        const float* Aptr = A + (size_t)(bm + arow) * K;

        unsigned long long acc2[8][4];
#pragma unroll
        for (int i = 0; i < 8; i++)
#pragma unroll
            for (int j = 0; j < 4; j++) acc2[i][j] = 0ull;

        {
            float4 av = make_float4(0.f, 0.f, 0.f, 0.f);
            float4 bv = make_float4(0.f, 0.f, 0.f, 0.f);
            if (acol4 < K) av = *(const float4*)(Aptr + acol4);
            if (brow  < K) bv = *(const float4*)(g_wit + (size_t)brow * N + bn + bcol4);
            As[0][acol4 + 0][arow] = av.x;
            As[0][acol4 + 1][arow] = av.y;
            As[0][acol4 + 2][arow] = av.z;
            As[0][acol4 + 3][arow] = av.w;
            *(float4*)&Bs[0][brow][bcol4] = bv;
        }
        __syncthreads();

        int p = 0;
        for (int k0 = 0; k0 < K; k0 += 8) {
            bool more = (k0 + 8) < K;
            float4 av2 = make_float4(0.f, 0.f, 0.f, 0.f);
            float4 bv2 = make_float4(0.f, 0.f, 0.f, 0.f);
            if (more) {
                int ac = k0 + 8 + acol4;
                int bk = k0 + 8 + brow;
                if (ac < K) av2 = *(const float4*)(Aptr + ac);
                if (bk < K) bv2 = *(const float4*)(g_wit + (size_t)bk * N + bn + bcol4);
            }
#pragma unroll
            for (int kk = 0; kk < 8; kk++) {
                float4 a0 = *(const float4*)&As[p][kk][ty * 8];
                float4 a1 = *(const float4*)&As[p][kk][ty * 8 + 4];
                const unsigned long long* bp =
                    (const unsigned long long*)&Bs[p][kk][tx * 8];
                unsigned long long bb0 = bp[0], bb1 = bp[1], bb2 = bp[2], bb3 = bp[3];
                float af[8] = {a0.x, a0.y, a0.z, a0.w, a1.x, a1.y, a1.z, a1.w};
#pragma unroll
                for (int i = 0; i < 8; i++) {
                    unsigned long long aa;
                    unsigned ai = __float_as_uint(af[i]);
                    asm("mov.b64 %0, {%1, %1};" : "=l"(aa) : "r"(ai));
                    FMA2(acc2[i][0], aa, bb0);
                    FMA2(acc2[i][1], aa, bb1);
                    FMA2(acc2[i][2], aa, bb2);
                    FMA2(acc2[i][3], aa, bb3);
                }
            }
            if (more) {
                As[p ^ 1][acol4 + 0][arow] = av2.x;
                As[p ^ 1][acol4 + 1][arow] = av2.y;
                As[p ^ 1][acol4 + 2][arow] = av2.z;
                As[p ^ 1][acol4 + 3][arow] = av2.w;
                *(float4*)&Bs[p ^ 1][brow][bcol4] = bv2;
            }
            __syncthreads();
            p ^= 1;
        }

        float biasv[8];
#pragma unroll
        for (int j = 0; j < 8; j++) {
            int n = bn + tx * 8 + j;
            biasv[j] = bi[n] + bh[n];
        }
#pragma unroll
        for (int i = 0; i < 8; i++) {
            size_t m = (size_t)(bm + ty * 8 + i);
            float r[8];
#pragma unroll
            for (int j = 0; j < 4; j++) {
                unsigned lo, hi;
                asm("mov.b64 {%0, %1}, %2;" : "=r"(lo), "=r"(hi) : "l"(acc2[i][j]));
                r[2 * j]     = __uint_as_float(lo) + biasv[2 * j];
                r[2 * j + 1] = __uint_as_float(hi) + biasv[2 * j + 1];
            }
            float4 v0 = make_float4(r[0], r[1], r[2], r[3]);
            float4 v1 = make_float4(r[4], r[5], r[6], r[7]);
            *(float4*)(g_hpre + m * HSZ + bn + tx * 8)     = v0;
            *(float4*)(g_hpre + m * HSZ + bn + tx * 8 + 4) = v1;
        }
        // acc regs only used after here; k-loop's last __syncthreads guards smem
    }
}

// ---------------------------------------------------------------------------
// Scan: cluster of 2 CTAs per batch pair; mbarrier-based ballot exchange
// (no barrier.cluster per step, no L1 flush). One __syncthreads per step.
// ---------------------------------------------------------------------------
#define NTH 288
#define SCAN_SMEM_FLOATS 39464   // 157,856 bytes

__device__ __forceinline__ void st_peer_u32(uint32_t local_addr, uint32_t rank,
                                            uint32_t val) {
    asm volatile(
        "{.reg .b32 ra; mapa.shared::cluster.u32 ra, %0, %1;"
        " st.shared::cluster.b32 [ra], %2;}"
        :: "r"(local_addr), "r"(rank), "r"(val) : "memory");
}

__device__ __forceinline__ void mbar_arrive_local(uint32_t mbar) {
    asm volatile("mbarrier.arrive.release.cta.shared::cta.b64 _, [%0];"
                 :: "r"(mbar) : "memory");
}

__device__ __forceinline__ void mbar_arrive_peer(uint32_t mbar, uint32_t rank) {
    asm volatile(
        "{.reg .b32 ra; mapa.shared::cluster.u32 ra, %0, %1;"
        " mbarrier.arrive.release.cluster.shared::cluster.b64 _, [ra];}"
        :: "r"(mbar), "r"(rank) : "memory");
}

__device__ __forceinline__ void mbar_wait_parity(uint32_t mbar, uint32_t parity) {
    uint32_t done;
    asm volatile(
        "{\n\t.reg .pred p;\n\t"
        "mbarrier.try_wait.parity.acquire.cluster.shared::cta.b64 p, [%1], %2;\n\t"
        "selp.b32 %0, 1, 0, p;\n\t}"
        : "=r"(done) : "r"(mbar), "r"(parity) : "memory");
    if (!done) {
        asm volatile(
            "{\n\t.reg .pred P1;\n\t"
            "WL_%=:\n\t"
            "mbarrier.try_wait.parity.acquire.cluster.shared::cta.b64 P1, [%0], %1, 0x989680;\n\t"
            "@P1 bra.uni WD_%=;\n\t"
            "bra.uni WL_%=;\n\t"
            "WD_%=:\n\t}"
            :: "r"(mbar), "r"(parity) : "memory");
    }
}

__device__ __forceinline__ uint32_t smem_u32(const void* p) {
    uint32_t a;
    asm("{ .reg .u64 t; cvta.to.shared.u64 t, %1; cvt.u32.u64 %0, t; }"
        : "=r"(a) : "l"(p));
    return a;
}

// bitwise-identical 8-wide reduction tree (same as R3)
#define TREE8(w0,w1,w2,w3,w4,w5,w6,w7) \
    (((w0 + w1) + (w2 + w3)) + ((w4 + w5) + (w6 + w7)))

__global__ void __launch_bounds__(NTH, 1) __cluster_dims__(2, 1, 1)
scan_kernel(const float* __restrict__ Wo,
            const float* __restrict__ bo_bias,
            const float* __restrict__ tau_adp_o,
            const float* __restrict__ tau_m_h,
            const float* __restrict__ tau_m_o,
            const float* __restrict__ h0,
            const float* __restrict__ o0,
            float* __restrict__ out)
{
    extern __shared__ float smf[];
    float*    s_wt   = smf;                        // [256][128]
    float*    s_woT  = smf + 32768;                // [256][20]
    float*    s_spk0 = smf + 37888;                // [2][256]
    int*      s_idx  = (int*)(smf + 38400);        // [2 parity][2 batch][256]
    unsigned* s_bal  = (unsigned*)(smf + 39424);   // [2 parity][16]
    unsigned long long* s_mbar = (unsigned long long*)(smf + 39456);

    const int tid  = threadIdx.x;
    const int lane = tid & 31;
    const int wid  = tid >> 5;
    const int r    = blockIdx.x & 1;
    const int b0   = blockIdx.x & ~1;
    const bool hidden = (wid < 8);

    // --- SMEM init ---
    for (int i = tid; i < 8192; i += NTH) {
        int j = i >> 5, c = i & 31;
        ((float4*)s_wt)[i] =
            *(const float4*)(g_wth + (size_t)j * HSZ + r * 128 + c * 4);
    }
    for (int i = tid; i < OSZ * HSZ; i += NTH) {
        int o = i >> 8, j = i & 255;
        s_woT[j * OSZ + o] = Wo[i];
    }
    for (int i = tid; i < 2 * HSZ; i += NTH) {
        int bl2 = i >> 8, j = i & 255;
        s_spk0[i] = h0[(size_t)(b0 + bl2) * HSZ + j];
    }
    if (tid == 0) {
        asm volatile("mbarrier.init.shared.b64 [%0], %1;"
                     :: "r"(smem_u32(s_mbar)), "r"(16u) : "memory");
    }

    const int bl = (hidden ? (tid >> 7) : 0);
    const int il = tid & 127;
    const int q  = (wid & 3);
    const int col = r * 128 + il;
    const int gw  = r * 4 + q;

    float a_h = 0.f, one_m_ah = 0.f, h_mem = 0.f, spf = 0.f;
    if (hidden) {
        a_h = expf(-1.f / tau_m_h[col]);
        one_m_ah = 1.f - a_h;
        h_mem = h0[(size_t)(b0 + bl) * HSZ + col];
        spf = h_mem;
    }

    float o_mem = 0.f, o_spk = 0.f, bo = 0.f;
    float alpha_o = 0.f, ro_o = 0.f, one_m_ao = 0.f, one_m_ro = 0.f, bias_o = 0.f;
    if (!hidden && lane < OSZ) {
        o_mem    = o0[(size_t)blockIdx.x * OSZ + lane];
        o_spk    = o_mem;
        bo       = BJ0;
        alpha_o  = expf(-1.f / tau_m_o[lane]);
        ro_o     = expf(-1.f / tau_adp_o[lane]);
        one_m_ao = 1.f - alpha_o;
        one_m_ro = 1.f - ro_o;
        bias_o   = bo_bias[lane];
    }
    __syncthreads();
    // mbarrier init + smem visible cluster-wide before any remote traffic
    asm volatile("barrier.cluster.arrive.aligned;" ::: "memory");
    asm volatile("barrier.cluster.wait.aligned;" ::: "memory");

    const float* hp = g_hpre + ((size_t)(b0 + bl) * TLEN) * HSZ + col;
    const float* wcol = s_wt + il;
    float pre = hidden ? __ldcs(hp) : 0.f;
    const uint32_t bal_base = smem_u32(s_bal);
    const uint32_t mbar_u32 = smem_u32(s_mbar);
    int cntA[2] = {0, 0};

#pragma unroll 1
    for (int t = 0; t <= TLEN; ++t) {
        // ---- A+B: wait for ballots(t-1), scatter to s_idx[t&1] ----
        if (t >= 1) {
            mbar_wait_parity(mbar_u32, (t - 1) & 1);
            const unsigned* wp0 = s_bal + ((t - 1) & 1) * 16;
            int* idx_buf = s_idx + (t & 1) * 512;
#pragma unroll
            for (int bb = 0; bb < 2; bb++) {
                const unsigned* wp = wp0 + bb * 8;
                unsigned w[8];
                int tot = 0;
#pragma unroll
                for (int k2 = 0; k2 < 8; k2++) { w[k2] = wp[k2]; tot += __popc(w[k2]); }
                cntA[bb] = tot;
                if (tid < HSZ) {
                    int wi = tid >> 5, bit = tid & 31;
                    if ((w[wi] >> bit) & 1u) {
                        int pos = 0;
#pragma unroll
                        for (int k2 = 0; k2 < 8; k2++)
                            if (k2 < wi) pos += __popc(w[k2]);
                        pos += __popc(w[wi] & ((1u << bit) - 1u));
                        idx_buf[bb * HSZ + pos] = tid;
                    }
                }
            }
        }
        __syncthreads();

        // ---- hidden: gather (software-pipelined, order-identical) ----
        if (hidden && t < TLEN) {
            float acc = pre;
            if (t + 1 < TLEN) pre = __ldcs(hp + (size_t)(t + 1) * HSZ);

            float racc = 0.f;
            if (t == 0) {
                const float* sp0 = s_spk0 + bl * HSZ;
#pragma unroll 8
                for (int j = 0; j < HSZ; ++j)
                    racc += wcol[j * 128] * sp0[j];
            } else {
                const int* lst = s_idx + (t & 1) * 512 + bl * HSZ;
                const int cnt = cntA[bl];
                int i = 0;
                if (cnt >= 8) {
                    int4 ja = *(const int4*)(lst);
                    int4 jb = *(const int4*)(lst + 4);
                    float w0 = wcol[ja.x * 128], w1 = wcol[ja.y * 128];
                    float w2 = wcol[ja.z * 128], w3 = wcol[ja.w * 128];
                    float w4 = wcol[jb.x * 128], w5 = wcol[jb.y * 128];
                    float w6 = wcol[jb.z * 128], w7 = wcol[jb.w * 128];
#pragma unroll 1
                    for (i = 8; i + 8 <= cnt; i += 8) {
                        int4 ja2 = *(const int4*)(lst + i);
                        int4 jb2 = *(const int4*)(lst + i + 4);
                        float v0 = wcol[ja2.x * 128], v1 = wcol[ja2.y * 128];
                        float v2 = wcol[ja2.z * 128], v3 = wcol[ja2.w * 128];
                        float v4 = wcol[jb2.x * 128], v5 = wcol[jb2.y * 128];
                        float v6 = wcol[jb2.z * 128], v7 = wcol[jb2.w * 128];
                        racc += TREE8(w0, w1, w2, w3, w4, w5, w6, w7);
                        w0 = v0; w1 = v1; w2 = v2; w3 = v3;
                        w4 = v4; w5 = v5; w6 = v6; w7 = v7;
                    }
                    racc += TREE8(w0, w1, w2, w3, w4, w5, w6, w7);
                }
#pragma unroll 1
                for (; i < cnt; ++i)
                    racc += wcol[lst[i] * 128];
            }
            acc += racc;

            h_mem = h_mem * a_h + one_m_ah * acc - BJ0 * spf;
            int sp = (h_mem - BJ0) > 0.f;
            spf = sp ? 1.f : 0.f;
            unsigned bal = __ballot_sync(0xffffffffu, sp);
            if (lane == 0) {
                int off = (t & 1) * 16 + bl * 8 + gw;
                s_bal[off] = bal;
                st_peer_u32(bal_base + off * 4, (unsigned)(r ^ 1), bal);
                mbar_arrive_local(mbar_u32);
                mbar_arrive_peer(mbar_u32, (unsigned)(r ^ 1));
            }
        }

        // ---- output warp: layer + log-softmax for step t-1 ----
        if (!hidden && t >= 1) {
            const int to = t - 1;
            float om;
            if (lane < OSZ) {
                float oin = bias_o;
                const int* lst = s_idx + (t & 1) * 512 + r * HSZ;
                const int cnt = cntA[r];
                int i = 0;
                if (cnt >= 8) {
                    int4 ja = *(const int4*)(lst);
                    int4 jb = *(const int4*)(lst + 4);
                    float w0 = s_woT[ja.x * OSZ + lane], w1 = s_woT[ja.y * OSZ + lane];
                    float w2 = s_woT[ja.z * OSZ + lane], w3 = s_woT[ja.w * OSZ + lane];
                    float w4 = s_woT[jb.x * OSZ + lane], w5 = s_woT[jb.y * OSZ + lane];
                    float w6 = s_woT[jb.z * OSZ + lane], w7 = s_woT[jb.w * OSZ + lane];
#pragma unroll 1
                    for (i = 8; i + 8 <= cnt; i += 8) {
                        int4 ja2 = *(const int4*)(lst + i);
                        int4 jb2 = *(const int4*)(lst + i + 4);
                        float v0 = s_woT[ja2.x * OSZ + lane], v1 = s_woT[ja2.y * OSZ + lane];
                        float v2 = s_woT[ja2.z * OSZ + lane], v3 = s_woT[ja2.w * OSZ + lane];
                        float v4 = s_woT[jb2.x * OSZ + lane], v5 = s_woT[jb2.y * OSZ + lane];
                        float v6 = s_woT[jb2.z * OSZ + lane], v7 = s_woT[jb2.w * OSZ + lane];
                        oin += TREE8(w0, w1, w2, w3, w4, w5, w6, w7);
                        w0 = v0; w1 = v1; w2 = v2; w3 = v3;
                        w4 = v4; w5 = v5; w6 = v6; w7 = v7;
                    }
                    oin += TREE8(w0, w1, w2, w3, w4, w5, w6, w7);
                }
#pragma unroll 1
                for (; i < cnt; ++i)
                    oin += s_woT[lst[i] * OSZ + lane];

                bo = ro_o * bo + one_m_ro * o_spk;
                float Bo = BJ0 + 1.8f * bo;
                o_mem = o_mem * alpha_o + one_m_ao * oin - Bo * o_spk;
                o_spk = ((o_mem - Bo) > 0.f) ? 1.f : 0.f;
                om = o_mem;
            } else {
                om = -CUDART_INF_F;
            }
            float mx = om;
#pragma unroll
            for (int off = 16; off; off >>= 1)
                mx = fmaxf(mx, __shfl_xor_sync(0xffffffffu, mx, off));
            float e = (lane < OSZ) ? expf(om - mx) : 0.f;
            float s = e;
#pragma unroll
            for (int off = 16; off; off >>= 1)
                s += __shfl_xor_sync(0xffffffffu, s, off);
            if (lane < OSZ)
                out[((size_t)blockIdx.x * OSZ + lane) * TLEN + to] = om - mx - logf(s);
        }
    }

    // peers may still target our smem until both exit the loop
    asm volatile("barrier.cluster.arrive.aligned;" ::: "memory");
    asm volatile("barrier.cluster.wait.aligned;" ::: "memory");
}

// ---------------------------------------------------------------------------
extern "C" void kernel_launch(void* const* d_in, const int* in_sizes, int n_in,
                              void* d_out, int out_size) {
    const float* x         = (const float*)d_in[0];
    const float* W_i2h     = (const float*)d_in[1];
    const float* b_i2h     = (const float*)d_in[2];
    const float* W_h2h     = (const float*)d_in[3];
    const float* b_h2h     = (const float*)d_in[4];
    const float* W_h2o     = (const float*)d_in[5];
    const float* b_h2o     = (const float*)d_in[6];
    const float* tau_adp_o = (const float*)d_in[8];
    const float* tau_m_h   = (const float*)d_in[9];
    const float* tau_m_o   = (const float*)d_in[10];
    const float* h0        = (const float*)d_in[11];
    const float* o0        = (const float*)d_in[12];
    float* out = (float*)d_out;

    prep_kernel<<<(ISZ * HSZ + 255) / 256, 256>>>(W_i2h, W_h2h);

    gemm_kernel<<<GEMM_GRID, 256>>>(x, b_i2h, b_h2h);

    static int smem_set = 0;
    if (!smem_set) {
        cudaFuncSetAttribute(scan_kernel,
                             cudaFuncAttributeMaxDynamicSharedMemorySize,
                             SCAN_SMEM_FLOATS * 4);
        smem_set = 1;
    }
    scan_kernel<<<BSZ, NTH, SCAN_SMEM_FLOATS * 4>>>(
        W_h2o, b_h2o, tau_adp_o, tau_m_h, tau_m_o, h0, o0, out);
}